// round 14
// baseline (speedup 1.0000x reference)
#include <cuda_runtime.h>
#include <cuda_fp16.h>
#include <cstdint>

#define TOKENS 8192
#define OUT_F  4096
#define IN_F   4096
#define GROUP  64
#define NGROUPS ((OUT_F * IN_F) / GROUP)   // 262144

#define BM 128
#define BN 256
#define BK 64
#define NKC (IN_F / BK)                    // 64 K-chunks
#define STAGES 3
#define ROWH 72                            // halfs per row (64 data + 8 pad)
#define ROWB 144                           // bytes per row
#define A_CHUNK_HALFS (BM * ROWH)          // 9216
#define B_CHUNK_HALFS (BN * ROWH)          // 18432
#define A_BYTES (BM * ROWB)                // 18432
#define B_BYTES (BN * ROWB)                // 36864
#define STAGE_BYTES (A_BYTES + B_BYTES)    // 55296
#define CTRL_BYTES 1024
#define SMEM_TOTAL (CTRL_BYTES + STAGES * STAGE_BYTES)  // 166912

#define NWARPS_C 16                        // compute warps (4 per SMSP)
#define NTHREADS (NWARPS_C * 32 + 32)      // 544: +1 producer warp

// Padded, tile-contiguous fp16 scratch (device globals: allocation-free).
__device__ __half g_x[(size_t)(TOKENS / BM) * NKC * A_CHUNK_HALFS];  // ~75 MB
__device__ __half g_w[(size_t)(OUT_F / BN) * NKC * B_CHUNK_HALFS];   // ~38 MB

// ---------------------------------------------------------------------------
// Fused prep: blocks [0, XB) convert x; blocks [XB, XB+WB) dequant W.
// ---------------------------------------------------------------------------
#define XB ((TOKENS * IN_F / 4) / 256)     // 32768
#define WB ((OUT_F * IN_F / 4) / 256)      // 16384

__global__ void prep_kernel(const float* __restrict__ x,
                            const int* __restrict__ Wq,
                            const float* __restrict__ scale,
                            const float* __restrict__ zero) {
    if (blockIdx.x < XB) {
        int i = blockIdx.x * 256 + threadIdx.x;          // one float4 of x
        float4 v = ((const float4*)x)[i];
        union { __half2 h[2]; uint2 u; } pk;
        pk.h[0] = __floats2half2_rn(v.x, v.y);
        pk.h[1] = __floats2half2_rn(v.z, v.w);
        int m  = i >> 10;                 // 1024 float4 per row
        int k  = (i & 1023) << 2;
        int mt = m >> 7, r = m & 127;
        int kc = k >> 6, c = k & 63;
        __half* dst = g_x + (size_t)(mt * NKC + kc) * A_CHUNK_HALFS + r * ROWH + c;
        *(uint2*)dst = pk.u;
    } else {
        int t = (blockIdx.x - XB) * 256 + threadIdx.x;   // 4 elements of W
        int idx = t << 2;
        int g = idx >> 6;
        int j = idx & 63;
        const int half_g = NGROUPS / 2;
        int pg = (g < half_g) ? g : (g - half_g);
        int4 q = *(const int4*)(Wq + (size_t)pg * GROUP + j);
        float z = zero[g], s = scale[g];
        float4 o;
        if (g < half_g) {
            o.x = ((float)((q.x >> 4) & 0xF) - z) * s;
            o.y = ((float)((q.y >> 4) & 0xF) - z) * s;
            o.z = ((float)((q.z >> 4) & 0xF) - z) * s;
            o.w = ((float)((q.w >> 4) & 0xF) - z) * s;
        } else {
            o.x = ((float)(q.x & 0xF) - z) * s;
            o.y = ((float)(q.y & 0xF) - z) * s;
            o.z = ((float)(q.z & 0xF) - z) * s;
            o.w = ((float)(q.w & 0xF) - z) * s;
        }
        union { __half2 h[2]; uint2 u; } pk;
        pk.h[0] = __floats2half2_rn(o.x, o.y);
        pk.h[1] = __floats2half2_rn(o.z, o.w);
        int n  = idx >> 12;
        int k  = idx & 4095;
        int nt = n >> 8, r = n & 255;
        int kc = k >> 6, c = k & 63;
        __half* dst = g_w + (size_t)(nt * NKC + kc) * B_CHUNK_HALFS + r * ROWH + c;
        *(uint2*)dst = pk.u;
    }
}

// ---------------------------------------------------------------------------
// sm_90-base async helpers (NO tcgen05 — ptxas target is sm_103, not sm_103a)
// ---------------------------------------------------------------------------
__device__ __forceinline__ void mbar_init(uint32_t mbar, uint32_t cnt) {
    asm volatile("mbarrier.init.shared.b64 [%0], %1;" :: "r"(mbar), "r"(cnt) : "memory");
}
__device__ __forceinline__ void mbar_arrive(uint32_t mbar) {
    asm volatile("mbarrier.arrive.release.cta.shared::cta.b64 _, [%0];"
                 :: "r"(mbar) : "memory");
}
__device__ __forceinline__ void mbar_expect_tx(uint32_t mbar, uint32_t bytes) {
    asm volatile("mbarrier.arrive.expect_tx.shared.b64 _, [%0], %1;"
                 :: "r"(mbar), "r"(bytes) : "memory");
}
__device__ __forceinline__ void mbar_wait(uint32_t mbar, uint32_t parity) {
    asm volatile(
        "{\n\t.reg .pred P;\n\t"
        "WL_%=:\n\t"
        "mbarrier.try_wait.parity.acquire.cta.shared::cta.b64 P, [%0], %1, 0x989680;\n\t"
        "@!P bra WL_%=;\n\t}"
        :: "r"(mbar), "r"(parity) : "memory");
}
__device__ __forceinline__ void bulk_g2s(uint32_t dst, const void* src,
                                         uint32_t bytes, uint32_t mbar) {
    asm volatile(
        "cp.async.bulk.shared::cluster.global.mbarrier::complete_tx::bytes "
        "[%0], [%1], %2, [%3];"
        :: "r"(dst), "l"(src), "r"(bytes), "r"(mbar) : "memory");
}
__device__ __forceinline__ void ldsm_x4(uint32_t* r, uint32_t addr) {
    asm volatile("ldmatrix.sync.aligned.m8n8.x4.shared.b16 {%0,%1,%2,%3}, [%4];"
                 : "=r"(r[0]), "=r"(r[1]), "=r"(r[2]), "=r"(r[3]) : "r"(addr));
}
__device__ __forceinline__ void mma16816(float* c, const uint32_t* a, const uint32_t* b) {
    asm volatile(
        "mma.sync.aligned.m16n8k16.row.col.f32.f16.f16.f32 "
        "{%0,%1,%2,%3}, {%4,%5,%6,%7}, {%8,%9}, {%0,%1,%2,%3};"
        : "+f"(c[0]), "+f"(c[1]), "+f"(c[2]), "+f"(c[3])
        : "r"(a[0]), "r"(a[1]), "r"(a[2]), "r"(a[3]), "r"(b[0]), "r"(b[1]));
}

// ---------------------------------------------------------------------------
// GEMM: out[M,N] = x[M,K] * W[N,K]^T + bias.  128x256x64 CTA tile.
// Warp-specialized: 16 compute warps (64x32 warp tiles) + 1 producer warp.
// Each warp walks the 4 k16-steps of a chunk in a ROTATED order (ks = ksi+wid
// mod 4) so LDSM bursts and HMMA chains of co-resident warps interleave
// instead of stalling in lock-step.
// ---------------------------------------------------------------------------
__global__ __launch_bounds__(NTHREADS, 1)
void gemm_kernel(const float* __restrict__ bias, float* __restrict__ out) {
    extern __shared__ __align__(1024) char smem[];
    uint32_t sb = (uint32_t)__cvta_generic_to_shared(smem);
    const int tid  = threadIdx.x;
    const int lane = tid & 31;
    const int wid  = tid >> 5;
    const int bn0  = blockIdx.x * BN;
    const int bm0  = blockIdx.y * BM;

    // full[s] at sb + s*8 ; empty[s] at sb + 32 + s*8
    if (tid == 0) {
        #pragma unroll
        for (int s = 0; s < STAGES; s++) {
            mbar_init(sb + s * 8, 1);
            mbar_init(sb + 32 + s * 8, NWARPS_C);
        }
        asm volatile("fence.proxy.async.shared::cta;" ::: "memory");
    }
    __syncthreads();

    if (wid == NWARPS_C) {
        // ------------------- producer warp (one thread) -------------------
        if (lane == 0) {
            const __half* Asrc = g_x + (size_t)blockIdx.y * NKC * A_CHUNK_HALFS;
            const __half* Bsrc = g_w + (size_t)blockIdx.x * NKC * B_CHUNK_HALFS;
            for (int kc = 0; kc < NKC; kc++) {
                int s = kc % STAGES;
                if (kc >= STAGES)
                    mbar_wait(sb + 32 + s * 8, ((kc / STAGES) - 1) & 1);
                mbar_expect_tx(sb + s * 8, STAGE_BYTES);
                uint32_t st = sb + CTRL_BYTES + s * STAGE_BYTES;
                bulk_g2s(st,           Asrc + (size_t)kc * A_CHUNK_HALFS, A_BYTES, sb + s * 8);
                bulk_g2s(st + A_BYTES, Bsrc + (size_t)kc * B_CHUNK_HALFS, B_BYTES, sb + s * 8);
            }
        }
        return;
    }

    // ------------------------ compute warps 0-15 -------------------------
    const int wm = wid >> 3;              // 0..1  (64 rows)
    const int wn = wid & 7;               // 0..7  (32 cols)
    const int ks_rot = wid & 3;           // per-warp k-step rotation

    float acc[4][4][4];
    #pragma unroll
    for (int a = 0; a < 4; a++)
        #pragma unroll
        for (int b = 0; b < 4; b++)
            #pragma unroll
            for (int c = 0; c < 4; c++) acc[a][b][c] = 0.0f;

    const int a_row = (lane & 15);
    const int a_col = (lane >> 4) * 16;                   // bytes
    const int b_row = (lane & 7) + ((lane & 16) >> 1);
    const int b_col = ((lane >> 3) & 1) * 16;             // bytes

    for (int c = 0; c < NKC; c++) {
        int slot = c % STAGES;
        mbar_wait(sb + slot * 8, (c / STAGES) & 1);

        uint32_t aBase = sb + CTRL_BYTES + slot * STAGE_BYTES;
        uint32_t bBase = aBase + A_BYTES;

        #pragma unroll
        for (int ksi = 0; ksi < 4; ksi++) {               // rotated k16 order
            int ks = (ksi + ks_rot) & 3;
            uint32_t af[4][4];
            #pragma unroll
            for (int mt = 0; mt < 4; mt++)
                ldsm_x4(af[mt], aBase + (uint32_t)(wm * 64 + mt * 16 + a_row) * ROWB
                                + ks * 32 + a_col);
            uint32_t bf[4][2];
            #pragma unroll
            for (int bt = 0; bt < 2; bt++) {
                uint32_t r4[4];
                ldsm_x4(r4, bBase + (uint32_t)(wn * 32 + bt * 16 + b_row) * ROWB
                             + ks * 32 + b_col);
                bf[2 * bt][0] = r4[0]; bf[2 * bt][1] = r4[1];
                bf[2 * bt + 1][0] = r4[2]; bf[2 * bt + 1][1] = r4[3];
            }
            #pragma unroll
            for (int mt = 0; mt < 4; mt++)
                #pragma unroll
                for (int nt = 0; nt < 4; nt++)
                    mma16816(acc[mt][nt], af[mt], bf[nt]);
        }

        // this warp is done reading slot: signal producer
        if (lane == 0) mbar_arrive(sb + 32 + slot * 8);
    }

    // Epilogue: +bias, float2 stores
    const int lr = lane >> 2;
    const int lc = lane & 3;
    #pragma unroll
    for (int mt = 0; mt < 4; mt++) {
        #pragma unroll
        for (int nt = 0; nt < 4; nt++) {
            int row = bm0 + wm * 64 + mt * 16 + lr;
            int col = bn0 + wn * 32 + nt * 8 + lc * 2;
            float b0 = __ldg(&bias[col]), b1 = __ldg(&bias[col + 1]);
            *(float2*)&out[(size_t)row * OUT_F + col] =
                make_float2(acc[mt][nt][0] + b0, acc[mt][nt][1] + b1);
            *(float2*)&out[(size_t)(row + 8) * OUT_F + col] =
                make_float2(acc[mt][nt][2] + b0, acc[mt][nt][3] + b1);
        }
    }
}

// ---------------------------------------------------------------------------
// Launch
// ---------------------------------------------------------------------------
extern "C" void kernel_launch(void* const* d_in, const int* in_sizes, int n_in,
                              void* d_out, int out_size) {
    const float* x     = (const float*)d_in[0];
    const int*   Wq    = (const int*)d_in[1];
    const float* scale = (const float*)d_in[2];
    const float* zero  = (const float*)d_in[3];
    const float* bias  = (const float*)d_in[4];
    float* out = (float*)d_out;

    prep_kernel<<<XB + WB, 256>>>(x, Wq, scale, zero);

    cudaFuncSetAttribute(gemm_kernel, cudaFuncAttributeMaxDynamicSharedMemorySize, SMEM_TOTAL);
    dim3 grid(OUT_F / BN, TOKENS / BM);   // (16, 64)
    gemm_kernel<<<grid, NTHREADS, SMEM_TOTAL>>>(bias, out);
}

// round 15
// speedup vs baseline: 1.0769x; 1.0769x over previous
#include <cuda_runtime.h>
#include <cuda_fp16.h>
#include <cstdint>

#define TOKENS 8192
#define OUT_F  4096
#define IN_F   4096
#define GROUP  64
#define NGROUPS ((OUT_F * IN_F) / GROUP)   // 262144

#define BM 128
#define BN 128
#define BK 64
#define NKC (IN_F / BK)                    // 64 K-chunks
#define STAGES 3
#define ROWH 72                            // halfs per row (64 data + 8 pad)
#define ROWB 144                           // bytes per row
#define A_CHUNK_HALFS (BM * ROWH)          // 9216
#define B_CHUNK_HALFS (BN * ROWH)          // 9216
#define A_BYTES (BM * ROWB)                // 18432
#define B_BYTES (BN * ROWB)                // 18432
#define STAGE_BYTES (A_BYTES + B_BYTES)    // 36864
#define CTRL_BYTES 1024
#define SMEM_TOTAL (CTRL_BYTES + STAGES * STAGE_BYTES)  // 111616 -> 2 CTAs/SM

#define NWARPS_C 4                         // compute warps (64x64 tiles)
#define NTHREADS (NWARPS_C * 32 + 32)      // 160: +1 producer warp

// Padded, tile-contiguous fp16 scratch (device globals: allocation-free).
__device__ __half g_x[(size_t)(TOKENS / BM) * NKC * A_CHUNK_HALFS];  // ~75 MB
__device__ __half g_w[(size_t)(OUT_F / BN) * NKC * B_CHUNK_HALFS];   // ~38 MB

// ---------------------------------------------------------------------------
// Fused prep: blocks [0, XB) convert x; blocks [XB, XB+WB) dequant W.
// ---------------------------------------------------------------------------
#define XB ((TOKENS * IN_F / 4) / 256)     // 32768
#define WB ((OUT_F * IN_F / 4) / 256)      // 16384

__global__ void prep_kernel(const float* __restrict__ x,
                            const int* __restrict__ Wq,
                            const float* __restrict__ scale,
                            const float* __restrict__ zero) {
    if (blockIdx.x < XB) {
        int i = blockIdx.x * 256 + threadIdx.x;          // one float4 of x
        float4 v = ((const float4*)x)[i];
        union { __half2 h[2]; uint2 u; } pk;
        pk.h[0] = __floats2half2_rn(v.x, v.y);
        pk.h[1] = __floats2half2_rn(v.z, v.w);
        int m  = i >> 10;                 // 1024 float4 per row
        int k  = (i & 1023) << 2;
        int mt = m >> 7, r = m & 127;
        int kc = k >> 6, c = k & 63;
        __half* dst = g_x + (size_t)(mt * NKC + kc) * A_CHUNK_HALFS + r * ROWH + c;
        *(uint2*)dst = pk.u;
    } else {
        int t = (blockIdx.x - XB) * 256 + threadIdx.x;   // 4 elements of W
        int idx = t << 2;
        int g = idx >> 6;
        int j = idx & 63;
        const int half_g = NGROUPS / 2;
        int pg = (g < half_g) ? g : (g - half_g);
        int4 q = *(const int4*)(Wq + (size_t)pg * GROUP + j);
        float z = zero[g], s = scale[g];
        float4 o;
        if (g < half_g) {
            o.x = ((float)((q.x >> 4) & 0xF) - z) * s;
            o.y = ((float)((q.y >> 4) & 0xF) - z) * s;
            o.z = ((float)((q.z >> 4) & 0xF) - z) * s;
            o.w = ((float)((q.w >> 4) & 0xF) - z) * s;
        } else {
            o.x = ((float)(q.x & 0xF) - z) * s;
            o.y = ((float)(q.y & 0xF) - z) * s;
            o.z = ((float)(q.z & 0xF) - z) * s;
            o.w = ((float)(q.w & 0xF) - z) * s;
        }
        union { __half2 h[2]; uint2 u; } pk;
        pk.h[0] = __floats2half2_rn(o.x, o.y);
        pk.h[1] = __floats2half2_rn(o.z, o.w);
        int n  = idx >> 12;
        int k  = idx & 4095;
        int nt = n >> 7, r = n & 127;     // BN = 128 tiles
        int kc = k >> 6, c = k & 63;
        __half* dst = g_w + (size_t)(nt * NKC + kc) * B_CHUNK_HALFS + r * ROWH + c;
        *(uint2*)dst = pk.u;
    }
}

// ---------------------------------------------------------------------------
// sm_90-base async helpers (NO tcgen05 — ptxas target is sm_103, not sm_103a)
// ---------------------------------------------------------------------------
__device__ __forceinline__ void mbar_init(uint32_t mbar, uint32_t cnt) {
    asm volatile("mbarrier.init.shared.b64 [%0], %1;" :: "r"(mbar), "r"(cnt) : "memory");
}
__device__ __forceinline__ void mbar_arrive(uint32_t mbar) {
    asm volatile("mbarrier.arrive.release.cta.shared::cta.b64 _, [%0];"
                 :: "r"(mbar) : "memory");
}
__device__ __forceinline__ void mbar_expect_tx(uint32_t mbar, uint32_t bytes) {
    asm volatile("mbarrier.arrive.expect_tx.shared.b64 _, [%0], %1;"
                 :: "r"(mbar), "r"(bytes) : "memory");
}
__device__ __forceinline__ void mbar_wait(uint32_t mbar, uint32_t parity) {
    asm volatile(
        "{\n\t.reg .pred P;\n\t"
        "WL_%=:\n\t"
        "mbarrier.try_wait.parity.acquire.cta.shared::cta.b64 P, [%0], %1, 0x989680;\n\t"
        "@!P bra WL_%=;\n\t}"
        :: "r"(mbar), "r"(parity) : "memory");
}
__device__ __forceinline__ void bulk_g2s(uint32_t dst, const void* src,
                                         uint32_t bytes, uint32_t mbar) {
    asm volatile(
        "cp.async.bulk.shared::cluster.global.mbarrier::complete_tx::bytes "
        "[%0], [%1], %2, [%3];"
        :: "r"(dst), "l"(src), "r"(bytes), "r"(mbar) : "memory");
}
__device__ __forceinline__ void ldsm_x4(uint32_t* r, uint32_t addr) {
    asm volatile("ldmatrix.sync.aligned.m8n8.x4.shared.b16 {%0,%1,%2,%3}, [%4];"
                 : "=r"(r[0]), "=r"(r[1]), "=r"(r[2]), "=r"(r[3]) : "r"(addr));
}
__device__ __forceinline__ void mma16816(float* c, const uint32_t* a, const uint32_t* b) {
    asm volatile(
        "mma.sync.aligned.m16n8k16.row.col.f32.f16.f16.f32 "
        "{%0,%1,%2,%3}, {%4,%5,%6,%7}, {%8,%9}, {%0,%1,%2,%3};"
        : "+f"(c[0]), "+f"(c[1]), "+f"(c[2]), "+f"(c[3])
        : "r"(a[0]), "r"(a[1]), "r"(a[2]), "r"(a[3]), "r"(b[0]), "r"(b[1]));
}

// ---------------------------------------------------------------------------
// GEMM: out[M,N] = x[M,K] * W[N,K]^T + bias.  128x128x64 CTA tile,
// 4 compute warps (64x64) + 1 producer warp, 2 CTAs per SM so the two CTAs'
// independent barrier phases interleave and cover each other's chunk-boundary
// stalls.
// ---------------------------------------------------------------------------
__global__ __launch_bounds__(NTHREADS, 2)
void gemm_kernel(const float* __restrict__ bias, float* __restrict__ out) {
    extern __shared__ __align__(1024) char smem[];
    uint32_t sb = (uint32_t)__cvta_generic_to_shared(smem);
    const int tid  = threadIdx.x;
    const int lane = tid & 31;
    const int wid  = tid >> 5;
    const int bn0  = blockIdx.x * BN;
    const int bm0  = blockIdx.y * BM;

    // full[s] at sb + s*8 ; empty[s] at sb + 32 + s*8
    if (tid == 0) {
        #pragma unroll
        for (int s = 0; s < STAGES; s++) {
            mbar_init(sb + s * 8, 1);
            mbar_init(sb + 32 + s * 8, NWARPS_C);
        }
        asm volatile("fence.proxy.async.shared::cta;" ::: "memory");
    }
    __syncthreads();

    if (wid == NWARPS_C) {
        // ------------------- producer warp (one thread) -------------------
        if (lane == 0) {
            const __half* Asrc = g_x + (size_t)blockIdx.y * NKC * A_CHUNK_HALFS;
            const __half* Bsrc = g_w + (size_t)blockIdx.x * NKC * B_CHUNK_HALFS;
            for (int kc = 0; kc < NKC; kc++) {
                int s = kc % STAGES;
                if (kc >= STAGES)
                    mbar_wait(sb + 32 + s * 8, ((kc / STAGES) - 1) & 1);
                mbar_expect_tx(sb + s * 8, STAGE_BYTES);
                uint32_t st = sb + CTRL_BYTES + s * STAGE_BYTES;
                bulk_g2s(st,           Asrc + (size_t)kc * A_CHUNK_HALFS, A_BYTES, sb + s * 8);
                bulk_g2s(st + A_BYTES, Bsrc + (size_t)kc * B_CHUNK_HALFS, B_BYTES, sb + s * 8);
            }
        }
        return;
    }

    // ------------------------- compute warps 0-3 -------------------------
    const int wm = wid >> 1;              // 0..1  (64 rows)
    const int wn = wid & 1;               // 0..1  (64 cols)

    float acc[4][8][4];
    #pragma unroll
    for (int a = 0; a < 4; a++)
        #pragma unroll
        for (int b = 0; b < 8; b++)
            #pragma unroll
            for (int c = 0; c < 4; c++) acc[a][b][c] = 0.0f;

    const int a_row = (lane & 15);
    const int a_col = (lane >> 4) * 16;                   // bytes
    const int b_row = (lane & 7) + ((lane & 16) >> 1);
    const int b_col = ((lane >> 3) & 1) * 16;             // bytes

    for (int c = 0; c < NKC; c++) {
        int slot = c % STAGES;
        mbar_wait(sb + slot * 8, (c / STAGES) & 1);

        uint32_t aBase = sb + CTRL_BYTES + slot * STAGE_BYTES;
        uint32_t bBase = aBase + A_BYTES;

        #pragma unroll
        for (int ks = 0; ks < 4; ks++) {                  // 4 x k16 per BK=64
            uint32_t af[4][4];
            #pragma unroll
            for (int mt = 0; mt < 4; mt++)
                ldsm_x4(af[mt], aBase + (uint32_t)(wm * 64 + mt * 16 + a_row) * ROWB
                                + ks * 32 + a_col);
            uint32_t bf[8][2];
            #pragma unroll
            for (int bt = 0; bt < 4; bt++) {
                uint32_t r4[4];
                ldsm_x4(r4, bBase + (uint32_t)(wn * 64 + bt * 16 + b_row) * ROWB
                             + ks * 32 + b_col);
                bf[2 * bt][0] = r4[0]; bf[2 * bt][1] = r4[1];
                bf[2 * bt + 1][0] = r4[2]; bf[2 * bt + 1][1] = r4[3];
            }
            #pragma unroll
            for (int mt = 0; mt < 4; mt++)
                #pragma unroll
                for (int nt = 0; nt < 8; nt++)
                    mma16816(acc[mt][nt], af[mt], bf[nt]);
        }

        // this warp is done reading slot: signal producer
        if (lane == 0) mbar_arrive(sb + 32 + slot * 8);
    }

    // Epilogue: +bias, float2 stores
    const int lr = lane >> 2;
    const int lc = lane & 3;
    #pragma unroll
    for (int mt = 0; mt < 4; mt++) {
        #pragma unroll
        for (int nt = 0; nt < 8; nt++) {
            int row = bm0 + wm * 64 + mt * 16 + lr;
            int col = bn0 + wn * 64 + nt * 8 + lc * 2;
            float b0 = __ldg(&bias[col]), b1 = __ldg(&bias[col + 1]);
            *(float2*)&out[(size_t)row * OUT_F + col] =
                make_float2(acc[mt][nt][0] + b0, acc[mt][nt][1] + b1);
            *(float2*)&out[(size_t)(row + 8) * OUT_F + col] =
                make_float2(acc[mt][nt][2] + b0, acc[mt][nt][3] + b1);
        }
    }
}

// ---------------------------------------------------------------------------
// Launch
// ---------------------------------------------------------------------------
extern "C" void kernel_launch(void* const* d_in, const int* in_sizes, int n_in,
                              void* d_out, int out_size) {
    const float* x     = (const float*)d_in[0];
    const int*   Wq    = (const int*)d_in[1];
    const float* scale = (const float*)d_in[2];
    const float* zero  = (const float*)d_in[3];
    const float* bias  = (const float*)d_in[4];
    float* out = (float*)d_out;

    prep_kernel<<<XB + WB, 256>>>(x, Wq, scale, zero);

    cudaFuncSetAttribute(gemm_kernel, cudaFuncAttributeMaxDynamicSharedMemorySize, SMEM_TOTAL);
    dim3 grid(OUT_F / BN, TOKENS / BM);   // (32, 64) = 2048 CTAs
    gemm_kernel<<<grid, NTHREADS, SMEM_TOTAL>>>(bias, out);
}

// round 16
// speedup vs baseline: 1.1214x; 1.0413x over previous
#include <cuda_runtime.h>
#include <cuda_fp16.h>
#include <cstdint>

#define TOKENS 8192
#define OUT_F  4096
#define IN_F   4096
#define GROUP  64
#define NGROUPS ((OUT_F * IN_F) / GROUP)   // 262144

#define BM 128
#define BN 128
#define BK 64
#define NKC (IN_F / BK)                    // 64 K-chunks
#define STAGES 3
#define ROWH 72                            // halfs per row (64 data + 8 pad)
#define ROWB 144                           // bytes per row
#define A_CHUNK_HALFS (BM * ROWH)          // 9216
#define B_CHUNK_HALFS (BN * ROWH)          // 9216
#define A_BYTES (BM * ROWB)                // 18432
#define B_BYTES (BN * ROWB)                // 18432
#define STAGE_BYTES (A_BYTES + B_BYTES)    // 36864
#define CTRL_BYTES 1024
#define SMEM_TOTAL (CTRL_BYTES + STAGES * STAGE_BYTES)  // 111616 -> 2 CTAs/SM

#define NWARPS_C 4                         // compute warps (64x64 tiles)
#define NTHREADS (NWARPS_C * 32 + 32)      // 160: +1 producer warp

// Padded, tile-contiguous fp16 scratch (device globals: allocation-free).
__device__ __half g_x[(size_t)(TOKENS / BM) * NKC * A_CHUNK_HALFS];  // ~75 MB
__device__ __half g_w[(size_t)(OUT_F / BN) * NKC * B_CHUNK_HALFS];   // ~38 MB

// ---------------------------------------------------------------------------
// Fused prep: blocks [0, XB) convert x; blocks [XB, XB+WB) dequant W.
// ---------------------------------------------------------------------------
#define XB ((TOKENS * IN_F / 4) / 256)     // 32768
#define WB ((OUT_F * IN_F / 4) / 256)      // 16384

__global__ void prep_kernel(const float* __restrict__ x,
                            const int* __restrict__ Wq,
                            const float* __restrict__ scale,
                            const float* __restrict__ zero) {
    if (blockIdx.x < XB) {
        int i = blockIdx.x * 256 + threadIdx.x;          // one float4 of x
        float4 v = ((const float4*)x)[i];
        union { __half2 h[2]; uint2 u; } pk;
        pk.h[0] = __floats2half2_rn(v.x, v.y);
        pk.h[1] = __floats2half2_rn(v.z, v.w);
        int m  = i >> 10;                 // 1024 float4 per row
        int k  = (i & 1023) << 2;
        int mt = m >> 7, r = m & 127;
        int kc = k >> 6, c = k & 63;
        __half* dst = g_x + (size_t)(mt * NKC + kc) * A_CHUNK_HALFS + r * ROWH + c;
        *(uint2*)dst = pk.u;
    } else {
        int t = (blockIdx.x - XB) * 256 + threadIdx.x;   // 4 elements of W
        int idx = t << 2;
        int g = idx >> 6;
        int j = idx & 63;
        const int half_g = NGROUPS / 2;
        int pg = (g < half_g) ? g : (g - half_g);
        int4 q = *(const int4*)(Wq + (size_t)pg * GROUP + j);
        float z = zero[g], s = scale[g];
        float4 o;
        if (g < half_g) {
            o.x = ((float)((q.x >> 4) & 0xF) - z) * s;
            o.y = ((float)((q.y >> 4) & 0xF) - z) * s;
            o.z = ((float)((q.z >> 4) & 0xF) - z) * s;
            o.w = ((float)((q.w >> 4) & 0xF) - z) * s;
        } else {
            o.x = ((float)(q.x & 0xF) - z) * s;
            o.y = ((float)(q.y & 0xF) - z) * s;
            o.z = ((float)(q.z & 0xF) - z) * s;
            o.w = ((float)(q.w & 0xF) - z) * s;
        }
        union { __half2 h[2]; uint2 u; } pk;
        pk.h[0] = __floats2half2_rn(o.x, o.y);
        pk.h[1] = __floats2half2_rn(o.z, o.w);
        int n  = idx >> 12;
        int k  = idx & 4095;
        int nt = n >> 7, r = n & 127;     // BN = 128 tiles
        int kc = k >> 6, c = k & 63;
        __half* dst = g_w + (size_t)(nt * NKC + kc) * B_CHUNK_HALFS + r * ROWH + c;
        *(uint2*)dst = pk.u;
    }
}

// ---------------------------------------------------------------------------
// sm_90-base async helpers (NO tcgen05 — ptxas target is sm_103, not sm_103a)
// ---------------------------------------------------------------------------
__device__ __forceinline__ void mbar_init(uint32_t mbar, uint32_t cnt) {
    asm volatile("mbarrier.init.shared.b64 [%0], %1;" :: "r"(mbar), "r"(cnt) : "memory");
}
__device__ __forceinline__ void mbar_arrive(uint32_t mbar) {
    asm volatile("mbarrier.arrive.release.cta.shared::cta.b64 _, [%0];"
                 :: "r"(mbar) : "memory");
}
__device__ __forceinline__ void mbar_expect_tx(uint32_t mbar, uint32_t bytes) {
    asm volatile("mbarrier.arrive.expect_tx.shared.b64 _, [%0], %1;"
                 :: "r"(mbar), "r"(bytes) : "memory");
}
__device__ __forceinline__ void mbar_wait(uint32_t mbar, uint32_t parity) {
    asm volatile(
        "{\n\t.reg .pred P;\n\t"
        "WL_%=:\n\t"
        "mbarrier.try_wait.parity.acquire.cta.shared::cta.b64 P, [%0], %1, 0x989680;\n\t"
        "@!P bra WL_%=;\n\t}"
        :: "r"(mbar), "r"(parity) : "memory");
}
__device__ __forceinline__ void bulk_g2s(uint32_t dst, const void* src,
                                         uint32_t bytes, uint32_t mbar) {
    asm volatile(
        "cp.async.bulk.shared::cluster.global.mbarrier::complete_tx::bytes "
        "[%0], [%1], %2, [%3];"
        :: "r"(dst), "l"(src), "r"(bytes), "r"(mbar) : "memory");
}
__device__ __forceinline__ void ldsm_x4(uint32_t* r, uint32_t addr) {
    asm volatile("ldmatrix.sync.aligned.m8n8.x4.shared.b16 {%0,%1,%2,%3}, [%4];"
                 : "=r"(r[0]), "=r"(r[1]), "=r"(r[2]), "=r"(r[3]) : "r"(addr));
}
__device__ __forceinline__ void mma16816(float* c, const uint32_t* a, const uint32_t* b) {
    asm volatile(
        "mma.sync.aligned.m16n8k16.row.col.f32.f16.f16.f32 "
        "{%0,%1,%2,%3}, {%4,%5,%6,%7}, {%8,%9}, {%0,%1,%2,%3};"
        : "+f"(c[0]), "+f"(c[1]), "+f"(c[2]), "+f"(c[3])
        : "r"(a[0]), "r"(a[1]), "r"(a[2]), "r"(a[3]), "r"(b[0]), "r"(b[1]));
}

// ---------------------------------------------------------------------------
// GEMM: out[M,N] = x[M,K] * W[N,K]^T + bias.  128x128x64 CTA tile,
// 4 compute warps (64x64) + 1 producer warp, 2 CTAs/SM.
// A-fragment prefetch: af(ks+1) LDSMs issue before MMAs(ks), hiding the
// LDSM->HMMA dependency bubble at 3 of 4 ks boundaries. Empty-arrive moves to
// right after the chunk's last LDSM (producer gets the slot ~250cyc earlier).
// ---------------------------------------------------------------------------
__global__ __launch_bounds__(NTHREADS, 2)
void gemm_kernel(const float* __restrict__ bias, float* __restrict__ out) {
    extern __shared__ __align__(1024) char smem[];
    uint32_t sb = (uint32_t)__cvta_generic_to_shared(smem);
    const int tid  = threadIdx.x;
    const int lane = tid & 31;
    const int wid  = tid >> 5;
    const int bn0  = blockIdx.x * BN;
    const int bm0  = blockIdx.y * BM;

    // full[s] at sb + s*8 ; empty[s] at sb + 32 + s*8
    if (tid == 0) {
        #pragma unroll
        for (int s = 0; s < STAGES; s++) {
            mbar_init(sb + s * 8, 1);
            mbar_init(sb + 32 + s * 8, NWARPS_C);
        }
        asm volatile("fence.proxy.async.shared::cta;" ::: "memory");
    }
    __syncthreads();

    if (wid == NWARPS_C) {
        // ------------------- producer warp (one thread) -------------------
        if (lane == 0) {
            const __half* Asrc = g_x + (size_t)blockIdx.y * NKC * A_CHUNK_HALFS;
            const __half* Bsrc = g_w + (size_t)blockIdx.x * NKC * B_CHUNK_HALFS;
            for (int kc = 0; kc < NKC; kc++) {
                int s = kc % STAGES;
                if (kc >= STAGES)
                    mbar_wait(sb + 32 + s * 8, ((kc / STAGES) - 1) & 1);
                mbar_expect_tx(sb + s * 8, STAGE_BYTES);
                uint32_t st = sb + CTRL_BYTES + s * STAGE_BYTES;
                bulk_g2s(st,           Asrc + (size_t)kc * A_CHUNK_HALFS, A_BYTES, sb + s * 8);
                bulk_g2s(st + A_BYTES, Bsrc + (size_t)kc * B_CHUNK_HALFS, B_BYTES, sb + s * 8);
            }
        }
        return;
    }

    // ------------------------- compute warps 0-3 -------------------------
    const int wm = wid >> 1;              // 0..1  (64 rows)
    const int wn = wid & 1;               // 0..1  (64 cols)

    float acc[4][8][4];
    #pragma unroll
    for (int a = 0; a < 4; a++)
        #pragma unroll
        for (int b = 0; b < 8; b++)
            #pragma unroll
            for (int c = 0; c < 4; c++) acc[a][b][c] = 0.0f;

    const int a_row = (lane & 15);
    const int a_col = (lane >> 4) * 16;                   // bytes
    const int b_row = (lane & 7) + ((lane & 16) >> 1);
    const int b_col = ((lane >> 3) & 1) * 16;             // bytes

    const uint32_t aOff = (uint32_t)(wm * 64 + a_row) * ROWB + a_col;
    const uint32_t bOff = (uint32_t)(wn * 64 + b_row) * ROWB + b_col;

    uint32_t af[2][4][4];                 // double-buffered A fragments

    for (int c = 0; c < NKC; c++) {
        int slot = c % STAGES;
        mbar_wait(sb + slot * 8, (c / STAGES) & 1);

        uint32_t aBase = sb + CTRL_BYTES + slot * STAGE_BYTES;
        uint32_t bBase = aBase + A_BYTES;

        // prime A fragments for ks=0
        #pragma unroll
        for (int mt = 0; mt < 4; mt++)
            ldsm_x4(af[0][mt], aBase + aOff + mt * (16 * ROWB));

        #pragma unroll
        for (int ks = 0; ks < 4; ks++) {                  // 4 x k16 per BK=64
            // B fragments for this ks
            uint32_t bf[8][2];
            #pragma unroll
            for (int bt = 0; bt < 4; bt++) {
                uint32_t r4[4];
                ldsm_x4(r4, bBase + bOff + bt * (16 * ROWB) + ks * 32);
                bf[2 * bt][0] = r4[0]; bf[2 * bt][1] = r4[1];
                bf[2 * bt + 1][0] = r4[2]; bf[2 * bt + 1][1] = r4[3];
            }
            // prefetch A fragments for ks+1 before issuing this ks's MMAs
            if (ks < 3) {
                #pragma unroll
                for (int mt = 0; mt < 4; mt++)
                    ldsm_x4(af[(ks + 1) & 1][mt],
                            aBase + aOff + mt * (16 * ROWB) + (ks + 1) * 32);
            } else {
                // all of this chunk's smem reads are issued; data lands in
                // registers synchronously -> release the slot to the producer
                if (lane == 0) mbar_arrive(sb + 32 + slot * 8);
            }
            #pragma unroll
            for (int mt = 0; mt < 4; mt++)
                #pragma unroll
                for (int nt = 0; nt < 8; nt++)
                    mma16816(acc[mt][nt], af[ks & 1][mt], bf[nt]);
        }
    }

    // Epilogue: +bias, float2 stores
    const int lr = lane >> 2;
    const int lc = lane & 3;
    #pragma unroll
    for (int mt = 0; mt < 4; mt++) {
        #pragma unroll
        for (int nt = 0; nt < 8; nt++) {
            int row = bm0 + wm * 64 + mt * 16 + lr;
            int col = bn0 + wn * 64 + nt * 8 + lc * 2;
            float b0 = __ldg(&bias[col]), b1 = __ldg(&bias[col + 1]);
            *(float2*)&out[(size_t)row * OUT_F + col] =
                make_float2(acc[mt][nt][0] + b0, acc[mt][nt][1] + b1);
            *(float2*)&out[(size_t)(row + 8) * OUT_F + col] =
                make_float2(acc[mt][nt][2] + b0, acc[mt][nt][3] + b1);
        }
    }
}

// ---------------------------------------------------------------------------
// Launch
// ---------------------------------------------------------------------------
extern "C" void kernel_launch(void* const* d_in, const int* in_sizes, int n_in,
                              void* d_out, int out_size) {
    const float* x     = (const float*)d_in[0];
    const int*   Wq    = (const int*)d_in[1];
    const float* scale = (const float*)d_in[2];
    const float* zero  = (const float*)d_in[3];
    const float* bias  = (const float*)d_in[4];
    float* out = (float*)d_out;

    prep_kernel<<<XB + WB, 256>>>(x, Wq, scale, zero);

    cudaFuncSetAttribute(gemm_kernel, cudaFuncAttributeMaxDynamicSharedMemorySize, SMEM_TOTAL);
    dim3 grid(OUT_F / BN, TOKENS / BM);   // (32, 64) = 2048 CTAs
    gemm_kernel<<<grid, NTHREADS, SMEM_TOTAL>>>(bias, out);
}